// round 2
// baseline (speedup 1.0000x reference)
#include <cuda_runtime.h>
#include <cuda_bf16.h>
#include <cstdint>
#include <cstddef>

// ---------------- problem constants ----------------
#define MAXM 8192
#define MAXN 4096
#define MAXK 4096

// quantized operands in device globals (allocation-free scratch)
__device__ uint8_t g_Xq[(size_t)MAXM * MAXK];   // Xq in [0,255]
__device__ int8_t  g_Wq[(size_t)MAXN * MAXK];   // Wq in [-127,127]
__device__ float   g_xs[MAXM];                  // activation scale per token
__device__ float   g_zp[MAXM];                  // activation zero point per token
__device__ float   g_ws[MAXN];                  // weight scale per row
__device__ float   g_wsum[MAXN];                // sum_k Wq[n,k] (integer-valued float)

// ---------------- helpers ----------------
__device__ __forceinline__ uint32_t smem_u32(const void* p) {
    return (uint32_t)__cvta_generic_to_shared(p);
}
__device__ __forceinline__ void cp16(uint32_t dst, const void* src) {
    asm volatile("cp.async.cg.shared.global [%0], [%1], 16;"
                 :: "r"(dst), "l"(__cvta_generic_to_global(src)) : "memory");
}
__device__ __forceinline__ void cp_commit() {
    asm volatile("cp.async.commit_group;" ::: "memory");
}
template <int N>
__device__ __forceinline__ void cp_wait_group() {
    asm volatile("cp.async.wait_group %0;" :: "n"(N) : "memory");
}
__device__ __forceinline__ void ldsm4(uint32_t& r0, uint32_t& r1, uint32_t& r2,
                                      uint32_t& r3, uint32_t addr) {
    asm volatile("ldmatrix.sync.aligned.m8n8.x4.shared.b16 {%0,%1,%2,%3}, [%4];"
                 : "=r"(r0), "=r"(r1), "=r"(r2), "=r"(r3) : "r"(addr));
}
__device__ __forceinline__ void imma16832(int32_t* d, const uint32_t* a,
                                          uint32_t b0, uint32_t b1) {
    asm volatile(
        "mma.sync.aligned.m16n8k32.row.col.s32.u8.s8.s32 "
        "{%0,%1,%2,%3}, {%4,%5,%6,%7}, {%8,%9}, {%0,%1,%2,%3};"
        : "+r"(d[0]), "+r"(d[1]), "+r"(d[2]), "+r"(d[3])
        : "r"(a[0]), "r"(a[1]), "r"(a[2]), "r"(a[3]), "r"(b0), "r"(b1));
}

// ---------------- block reductions ----------------
__device__ __forceinline__ float blockReduceMaxF(float v) {
    __shared__ float sh[8];
    #pragma unroll
    for (int o = 16; o; o >>= 1) v = fmaxf(v, __shfl_xor_sync(0xffffffffu, v, o));
    int wid = threadIdx.x >> 5, lid = threadIdx.x & 31;
    if (lid == 0) sh[wid] = v;
    __syncthreads();
    if (threadIdx.x < 32) {
        float t = (lid < 8) ? sh[lid] : -3.4e38f;
        #pragma unroll
        for (int o = 4; o; o >>= 1) t = fmaxf(t, __shfl_xor_sync(0xffffffffu, t, o));
        if (lid == 0) sh[0] = t;
    }
    __syncthreads();
    float r = sh[0];
    __syncthreads();
    return r;
}
__device__ __forceinline__ float blockReduceSumF(float v) {
    __shared__ float sh[8];
    #pragma unroll
    for (int o = 16; o; o >>= 1) v += __shfl_xor_sync(0xffffffffu, v, o);
    int wid = threadIdx.x >> 5, lid = threadIdx.x & 31;
    if (lid == 0) sh[wid] = v;
    __syncthreads();
    if (threadIdx.x < 32) {
        float t = (lid < 8) ? sh[lid] : 0.f;
        #pragma unroll
        for (int o = 4; o; o >>= 1) t += __shfl_xor_sync(0xffffffffu, t, o);
        if (lid == 0) sh[0] = t;
    }
    __syncthreads();
    float r = sh[0];
    __syncthreads();
    return r;
}

// ---------------- quantization kernels ----------------
__global__ void __launch_bounds__(256) quant_w_kernel(const float* __restrict__ W, int K) {
    int n = blockIdx.x;
    const float4* row = (const float4*)(W + (size_t)n * K);
    int nv = K >> 2;
    float amax = 0.f;
    for (int i = threadIdx.x; i < nv; i += blockDim.x) {
        float4 v = row[i];
        amax = fmaxf(amax, fmaxf(fmaxf(fabsf(v.x), fabsf(v.y)),
                                 fmaxf(fabsf(v.z), fabsf(v.w))));
    }
    amax = blockReduceMaxF(amax);
    float scale = (amax > 0.f) ? (amax / 127.0f) : 1.0f;
    if (threadIdx.x == 0) g_ws[n] = scale;
    char4* o = (char4*)(g_Wq + (size_t)n * K);
    float ssum = 0.f;
    for (int i = threadIdx.x; i < nv; i += blockDim.x) {
        float4 v = row[i];
        float q0 = fminf(fmaxf(rintf(v.x / scale), -127.f), 127.f);
        float q1 = fminf(fmaxf(rintf(v.y / scale), -127.f), 127.f);
        float q2 = fminf(fmaxf(rintf(v.z / scale), -127.f), 127.f);
        float q3 = fminf(fmaxf(rintf(v.w / scale), -127.f), 127.f);
        ssum += q0 + q1 + q2 + q3;
        char4 c;
        c.x = (char)(int)q0; c.y = (char)(int)q1;
        c.z = (char)(int)q2; c.w = (char)(int)q3;
        o[i] = c;
    }
    ssum = blockReduceSumF(ssum);
    if (threadIdx.x == 0) g_wsum[n] = ssum;
}

__global__ void __launch_bounds__(256) quant_x_kernel(const float* __restrict__ X, int K) {
    int m = blockIdx.x;
    const float4* row = (const float4*)(X + (size_t)m * K);
    int nv = K >> 2;
    float vmax = -3.4e38f, nvmin = -3.4e38f;  // nvmin = max(-x)
    for (int i = threadIdx.x; i < nv; i += blockDim.x) {
        float4 v = row[i];
        vmax  = fmaxf(vmax,  fmaxf(fmaxf(v.x, v.y), fmaxf(v.z, v.w)));
        nvmin = fmaxf(nvmin, fmaxf(fmaxf(-v.x, -v.y), fmaxf(-v.z, -v.w)));
    }
    vmax  = blockReduceMaxF(vmax);
    nvmin = blockReduceMaxF(nvmin);
    float vmin = -nvmin;
    float rng = vmax - vmin;
    float scale = (rng > 0.f) ? (rng / 255.0f) : 1.0f;
    float zp = rintf(-vmin / scale);
    if (threadIdx.x == 0) { g_xs[m] = scale; g_zp[m] = zp; }
    uchar4* o = (uchar4*)(g_Xq + (size_t)m * K);
    for (int i = threadIdx.x; i < nv; i += blockDim.x) {
        float4 v = row[i];
        float q0 = fminf(fmaxf(rintf(v.x / scale) + zp, 0.f), 255.f);
        float q1 = fminf(fmaxf(rintf(v.y / scale) + zp, 0.f), 255.f);
        float q2 = fminf(fmaxf(rintf(v.z / scale) + zp, 0.f), 255.f);
        float q3 = fminf(fmaxf(rintf(v.w / scale) + zp, 0.f), 255.f);
        uchar4 c;
        c.x = (unsigned char)(int)q0; c.y = (unsigned char)(int)q1;
        c.z = (unsigned char)(int)q2; c.w = (unsigned char)(int)q3;
        o[i] = c;
    }
}

// ---------------- int8 GEMM (IMMA via mma.sync) ----------------
#define BM 128
#define BN 128
#define BKB 128                       // K-bytes (int8 elems) per stage
#define STAGES 4
#define AS_BYTES (BM * BKB)           // 16 KB
#define BS_BYTES (BN * BKB)           // 16 KB
#define STAGE_BYTES (AS_BYTES + BS_BYTES)   // 32 KB
#define GEMM_SMEM (STAGES * STAGE_BYTES)    // 128 KB

__device__ __forceinline__ void load_stage_i8(uint32_t smem_base, int s, int kc,
                                              int m_base, int n_base, int K, int tid) {
    uint32_t a_smem = smem_base + s * STAGE_BYTES;
    uint32_t b_smem = a_smem + AS_BYTES;
    size_t koff = (size_t)kc * BKB;
    // A: 128 rows x 8 x 16B = 1024 chunks / 256 threads = 4 each
    #pragma unroll
    for (int it = 0; it < 4; it++) {
        int c = tid + it * 256;
        int row = c >> 3, ch = c & 7;
        const void* src = g_Xq + (size_t)(m_base + row) * K + koff + ch * 16;
        cp16(a_smem + row * 128 + ((ch ^ (row & 7)) * 16), src);
    }
    // B: 128 rows x 8 x 16B
    #pragma unroll
    for (int it = 0; it < 4; it++) {
        int c = tid + it * 256;
        int row = c >> 3, ch = c & 7;
        const void* src = g_Wq + (size_t)(n_base + row) * K + koff + ch * 16;
        cp16(b_smem + row * 128 + ((ch ^ (row & 7)) * 16), src);
    }
}

__global__ void __launch_bounds__(256, 1)
qgemm_kernel(const float* __restrict__ bias, float* __restrict__ out,
             int M, int N, int K) {
    extern __shared__ char smem[];
    const int tid  = threadIdx.x;
    const int wid  = tid >> 5;
    const int lane = tid & 31;
    const int wm   = wid >> 2;        // 0..1  (64-row slab)
    const int wn   = wid & 3;         // 0..3  (32-col slab)
    uint32_t smem_base = smem_u32(smem);

    const int m_base = blockIdx.y * BM;
    const int n_base = blockIdx.x * BN;

    int32_t acc[4][4][4];             // [mt][nt][reg]
    #pragma unroll
    for (int mt = 0; mt < 4; mt++)
        #pragma unroll
        for (int nt = 0; nt < 4; nt++)
            #pragma unroll
            for (int r = 0; r < 4; r++) acc[mt][nt][r] = 0;

    const int iters = K / BKB;        // 32

    // per-thread invariant addresses
    const int rowA   = wm * 64 + (lane & 15);     // + mt*16
    const int halfA  = lane >> 4;                 // chunk low bit
    const int swzA   = rowA & 7;
    const int rowB   = wn * 32 + lane;
    const int swzB   = lane & 7;

    #pragma unroll
    for (int i = 0; i < STAGES - 1; i++) {
        load_stage_i8(smem_base, i, i, m_base, n_base, K, tid);
        cp_commit();
    }

    for (int i = 0; i < iters; i++) {
        int s = i % STAGES;
        cp_wait_group<STAGES - 2>();
        __syncthreads();

        uint32_t a_base = smem_base + s * STAGE_BYTES;
        uint32_t b_base = a_base + AS_BYTES;

        #pragma unroll
        for (int ks = 0; ks < 4; ks++) {
            uint32_t b0[4], b1[4];
            ldsm4(b0[0], b0[1], b0[2], b0[3],
                  b_base + rowB * 128 + (((2 * ks)     ^ swzB) * 16));
            ldsm4(b1[0], b1[1], b1[2], b1[3],
                  b_base + rowB * 128 + (((2 * ks + 1) ^ swzB) * 16));
            #pragma unroll
            for (int mt = 0; mt < 4; mt++) {
                uint32_t a[4];
                ldsm4(a[0], a[1], a[2], a[3],
                      a_base + (rowA + mt * 16) * 128 +
                      (((2 * ks + halfA) ^ swzA) * 16));
                #pragma unroll
                for (int nt = 0; nt < 4; nt++)
                    imma16832(acc[mt][nt], a, b0[nt], b1[nt]);
            }
        }

        int j = i + STAGES - 1;
        if (j < iters)
            load_stage_i8(smem_base, j % STAGES, j, m_base, n_base, K, tid);
        cp_commit();
    }

    // ---------------- epilogue ----------------
    // n-values this thread owns: nt*8 + (lane&3)*2 + {0,1}
    float wsn[8], wss[8], bv[8];
    #pragma unroll
    for (int nt = 0; nt < 4; nt++) {
        #pragma unroll
        for (int j = 0; j < 2; j++) {
            int n = n_base + wn * 32 + nt * 8 + (lane & 3) * 2 + j;
            wsn[nt * 2 + j] = g_wsum[n];
            wss[nt * 2 + j] = g_ws[n];
            bv[nt * 2 + j]  = bias[n];
        }
    }
    #pragma unroll
    for (int mt = 0; mt < 4; mt++) {
        #pragma unroll
        for (int p = 0; p < 2; p++) {
            int m = m_base + wm * 64 + mt * 16 + (lane >> 2) + p * 8;
            float cs = g_xs[m];
            float zp = g_zp[m];
            float* orow = out + (size_t)m * N + n_base + wn * 32;
            #pragma unroll
            for (int nt = 0; nt < 4; nt++) {
                float2 o;
                float v0 = (float)acc[mt][nt][p * 2 + 0];
                float v1 = (float)acc[mt][nt][p * 2 + 1];
                o.x = (v0 - zp * wsn[nt * 2 + 0]) * (cs * wss[nt * 2 + 0]) + bv[nt * 2 + 0];
                o.y = (v1 - zp * wsn[nt * 2 + 1]) * (cs * wss[nt * 2 + 1]) + bv[nt * 2 + 1];
                *reinterpret_cast<float2*>(orow + nt * 8 + (lane & 3) * 2) = o;
            }
        }
    }
}

// ---------------- launcher ----------------
extern "C" void kernel_launch(void* const* d_in, const int* in_sizes, int n_in,
                              void* d_out, int out_size) {
    const float* x    = (const float*)d_in[0];
    const float* w    = (const float*)d_in[1];
    const float* bias = (const float*)d_in[2];
    int N = in_sizes[2];                  // 4096
    int K = in_sizes[1] / N;              // 4096
    int M = in_sizes[0] / K;              // 8192

    quant_w_kernel<<<N, 256>>>(w, K);
    quant_x_kernel<<<M, 256>>>(x, K);

    cudaFuncSetAttribute(qgemm_kernel, cudaFuncAttributeMaxDynamicSharedMemorySize,
                         GEMM_SMEM);
    dim3 grid(N / BN, M / BM);
    qgemm_kernel<<<grid, 256, GEMM_SMEM>>>(bias, (float*)d_out, M, N, K);
}

// round 3
// speedup vs baseline: 2.4512x; 2.4512x over previous
#include <cuda_runtime.h>
#include <cuda_bf16.h>
#include <cstdint>
#include <cstddef>

// ---------------- problem constants ----------------
#define MAXM 8192
#define MAXN 4096
#define MAXK 4096

// quantized operands in device globals (allocation-free scratch)
// g_Xq holds (Xq - zp): exact integers in [-255,255], bf16-exact.
// g_Wq holds Wq:        exact integers in [-127,127], bf16-exact.
__device__ __nv_bfloat16 g_Xq[(size_t)MAXM * MAXK];
__device__ __nv_bfloat16 g_Wq[(size_t)MAXN * MAXK];
__device__ float g_xs[MAXM];   // activation scale per token
__device__ float g_ws[MAXN];   // weight scale per row

// ---------------- helpers ----------------
__device__ __forceinline__ uint32_t smem_u32(const void* p) {
    return (uint32_t)__cvta_generic_to_shared(p);
}
__device__ __forceinline__ void cp16(uint32_t dst, const void* src) {
    asm volatile("cp.async.cg.shared.global [%0], [%1], 16;"
                 :: "r"(dst), "l"(__cvta_generic_to_global(src)) : "memory");
}
__device__ __forceinline__ void cp_commit() {
    asm volatile("cp.async.commit_group;" ::: "memory");
}
template <int N>
__device__ __forceinline__ void cp_wait_group() {
    asm volatile("cp.async.wait_group %0;" :: "n"(N) : "memory");
}
__device__ __forceinline__ void ldsm4(uint32_t& r0, uint32_t& r1, uint32_t& r2,
                                      uint32_t& r3, uint32_t addr) {
    asm volatile("ldmatrix.sync.aligned.m8n8.x4.shared.b16 {%0,%1,%2,%3}, [%4];"
                 : "=r"(r0), "=r"(r1), "=r"(r2), "=r"(r3) : "r"(addr));
}
__device__ __forceinline__ void hmma16816(float* d, const uint32_t* a,
                                          uint32_t b0, uint32_t b1) {
    asm volatile(
        "mma.sync.aligned.m16n8k16.row.col.f32.bf16.bf16.f32 "
        "{%0,%1,%2,%3}, {%4,%5,%6,%7}, {%8,%9}, {%0,%1,%2,%3};"
        : "+f"(d[0]), "+f"(d[1]), "+f"(d[2]), "+f"(d[3])
        : "r"(a[0]), "r"(a[1]), "r"(a[2]), "r"(a[3]), "r"(b0), "r"(b1));
}

// ---------------- block reductions ----------------
__device__ __forceinline__ float blockReduceMaxF(float v) {
    __shared__ float sh[8];
    #pragma unroll
    for (int o = 16; o; o >>= 1) v = fmaxf(v, __shfl_xor_sync(0xffffffffu, v, o));
    int wid = threadIdx.x >> 5, lid = threadIdx.x & 31;
    if (lid == 0) sh[wid] = v;
    __syncthreads();
    if (threadIdx.x < 32) {
        float t = (lid < 8) ? sh[lid] : -3.4e38f;
        #pragma unroll
        for (int o = 4; o; o >>= 1) t = fmaxf(t, __shfl_xor_sync(0xffffffffu, t, o));
        if (lid == 0) sh[0] = t;
    }
    __syncthreads();
    float r = sh[0];
    __syncthreads();
    return r;
}

// ---------------- quantization kernels ----------------
__global__ void __launch_bounds__(256) quant_w_kernel(const float* __restrict__ W, int K) {
    int n = blockIdx.x;
    const float4* row = (const float4*)(W + (size_t)n * K);
    int nv = K >> 2;
    float amax = 0.f;
    for (int i = threadIdx.x; i < nv; i += blockDim.x) {
        float4 v = row[i];
        amax = fmaxf(amax, fmaxf(fmaxf(fabsf(v.x), fabsf(v.y)),
                                 fmaxf(fabsf(v.z), fabsf(v.w))));
    }
    amax = blockReduceMaxF(amax);
    float scale = (amax > 0.f) ? (amax / 127.0f) : 1.0f;
    if (threadIdx.x == 0) g_ws[n] = scale;
    __nv_bfloat16* o = g_Wq + (size_t)n * K;
    for (int i = threadIdx.x; i < nv; i += blockDim.x) {
        float4 v = row[i];
        float q0 = fminf(fmaxf(rintf(v.x / scale), -127.f), 127.f);
        float q1 = fminf(fmaxf(rintf(v.y / scale), -127.f), 127.f);
        float q2 = fminf(fmaxf(rintf(v.z / scale), -127.f), 127.f);
        float q3 = fminf(fmaxf(rintf(v.w / scale), -127.f), 127.f);
        uint2 u;
        u.x = ((uint32_t)__bfloat16_as_ushort(__float2bfloat16(q1)) << 16) |
               (uint32_t)__bfloat16_as_ushort(__float2bfloat16(q0));
        u.y = ((uint32_t)__bfloat16_as_ushort(__float2bfloat16(q3)) << 16) |
               (uint32_t)__bfloat16_as_ushort(__float2bfloat16(q2));
        *reinterpret_cast<uint2*>(o + 4 * (size_t)i) = u;
    }
}

__global__ void __launch_bounds__(256) quant_x_kernel(const float* __restrict__ X, int K) {
    int m = blockIdx.x;
    const float4* row = (const float4*)(X + (size_t)m * K);
    int nv = K >> 2;
    float vmax = -3.4e38f, nvmin = -3.4e38f;  // nvmin = max(-x)
    for (int i = threadIdx.x; i < nv; i += blockDim.x) {
        float4 v = row[i];
        vmax  = fmaxf(vmax,  fmaxf(fmaxf(v.x, v.y), fmaxf(v.z, v.w)));
        nvmin = fmaxf(nvmin, fmaxf(fmaxf(-v.x, -v.y), fmaxf(-v.z, -v.w)));
    }
    vmax  = blockReduceMaxF(vmax);
    nvmin = blockReduceMaxF(nvmin);
    float vmin = -nvmin;
    float rng = vmax - vmin;
    float scale = (rng > 0.f) ? (rng / 255.0f) : 1.0f;
    float zp = rintf(-vmin / scale);
    if (threadIdx.x == 0) g_xs[m] = scale;
    __nv_bfloat16* o = g_Xq + (size_t)m * K;
    for (int i = threadIdx.x; i < nv; i += blockDim.x) {
        float4 v = row[i];
        // (clip(round(x/s)+zp, 0, 255) - zp) : exact integer in [-255,255]
        float q0 = fminf(fmaxf(rintf(v.x / scale) + zp, 0.f), 255.f) - zp;
        float q1 = fminf(fmaxf(rintf(v.y / scale) + zp, 0.f), 255.f) - zp;
        float q2 = fminf(fmaxf(rintf(v.z / scale) + zp, 0.f), 255.f) - zp;
        float q3 = fminf(fmaxf(rintf(v.w / scale) + zp, 0.f), 255.f) - zp;
        uint2 u;
        u.x = ((uint32_t)__bfloat16_as_ushort(__float2bfloat16(q1)) << 16) |
               (uint32_t)__bfloat16_as_ushort(__float2bfloat16(q0));
        u.y = ((uint32_t)__bfloat16_as_ushort(__float2bfloat16(q3)) << 16) |
               (uint32_t)__bfloat16_as_ushort(__float2bfloat16(q2));
        *reinterpret_cast<uint2*>(o + 4 * (size_t)i) = u;
    }
}

// ---------------- bf16 GEMM (HMMA via mma.sync) ----------------
#define BM 128
#define BN 128
#define BK 64                          // bf16 elems per K-chunk = 128 bytes/row
#define STAGES 4
#define AS_BYTES (BM * 128)            // 16 KB
#define BS_BYTES (BN * 128)            // 16 KB
#define STAGE_BYTES (AS_BYTES + BS_BYTES)   // 32 KB
#define GEMM_SMEM (STAGES * STAGE_BYTES)    // 128 KB

__device__ __forceinline__ void load_stage_bf16(uint32_t smem_base, int s, int kc,
                                                int m_base, int n_base, int K, int tid) {
    uint32_t a_smem = smem_base + s * STAGE_BYTES;
    uint32_t b_smem = a_smem + AS_BYTES;
    const char* Abase = (const char*)g_Xq;
    const char* Bbase = (const char*)g_Wq;
    size_t koff = (size_t)kc * BK * 2;     // bytes
    // A: 128 rows x 8 x 16B = 1024 chunks / 256 threads = 4 each
    #pragma unroll
    for (int it = 0; it < 4; it++) {
        int c = tid + it * 256;
        int row = c >> 3, ch = c & 7;
        const void* src = Abase + ((size_t)(m_base + row) * K) * 2 + koff + ch * 16;
        cp16(a_smem + row * 128 + ((ch ^ (row & 7)) * 16), src);
    }
    // B: 128 rows x 8 x 16B
    #pragma unroll
    for (int it = 0; it < 4; it++) {
        int c = tid + it * 256;
        int row = c >> 3, ch = c & 7;
        const void* src = Bbase + ((size_t)(n_base + row) * K) * 2 + koff + ch * 16;
        cp16(b_smem + row * 128 + ((ch ^ (row & 7)) * 16), src);
    }
}

__global__ void __launch_bounds__(256, 1)
qgemm_kernel(const float* __restrict__ bias, float* __restrict__ out,
             int M, int N, int K) {
    extern __shared__ char smem[];
    const int tid  = threadIdx.x;
    const int wid  = tid >> 5;
    const int lane = tid & 31;
    const int wm   = wid >> 2;        // 0..1  (64-row slab)
    const int wn   = wid & 3;         // 0..3  (32-col slab)
    uint32_t smem_base = smem_u32(smem);

    const int m_base = blockIdx.y * BM;
    const int n_base = blockIdx.x * BN;

    float acc[4][4][4];               // [mt][nt][reg], nt = n8 block 0..3
    #pragma unroll
    for (int mt = 0; mt < 4; mt++)
        #pragma unroll
        for (int nt = 0; nt < 4; nt++)
            #pragma unroll
            for (int r = 0; r < 4; r++) acc[mt][nt][r] = 0.f;

    const int iters = K / BK;         // 64

    // per-thread invariant addressing
    const int rowA  = wm * 64 + (lane & 15);   // + mt*16
    const int halfA = lane >> 4;               // 16B chunk low bit (k half)
    const int swzA  = rowA & 7;
    const int rowB0 = wn * 32 + (lane & 15);   // + nt2*16
    const int swzB  = lane & 7;

    #pragma unroll
    for (int i = 0; i < STAGES - 1; i++) {
        load_stage_bf16(smem_base, i, i, m_base, n_base, K, tid);
        cp_commit();
    }

    for (int i = 0; i < iters; i++) {
        int s = i % STAGES;
        cp_wait_group<STAGES - 2>();
        __syncthreads();

        uint32_t a_base = smem_base + s * STAGE_BYTES;
        uint32_t b_base = a_base + AS_BYTES;

        #pragma unroll
        for (int ks = 0; ks < 4; ks++) {
            // B: two ldsm.x4 (n16 each) -> fragments for 4 n8 blocks at this ks
            uint32_t bq0[4], bq1[4];
            ldsm4(bq0[0], bq0[1], bq0[2], bq0[3],
                  b_base + rowB0 * 128 + (((2 * ks + halfA) ^ swzB) * 16));
            ldsm4(bq1[0], bq1[1], bq1[2], bq1[3],
                  b_base + (rowB0 + 16) * 128 + (((2 * ks + halfA) ^ swzB) * 16));
            #pragma unroll
            for (int mt = 0; mt < 4; mt++) {
                uint32_t a[4];
                ldsm4(a[0], a[1], a[2], a[3],
                      a_base + (rowA + mt * 16) * 128 +
                      (((2 * ks + halfA) ^ swzA) * 16));
                hmma16816(acc[mt][0], a, bq0[0], bq0[2]);  // n 0-7
                hmma16816(acc[mt][1], a, bq0[1], bq0[3]);  // n 8-15
                hmma16816(acc[mt][2], a, bq1[0], bq1[2]);  // n 16-23
                hmma16816(acc[mt][3], a, bq1[1], bq1[3]);  // n 24-31
            }
        }

        int j = i + STAGES - 1;
        if (j < iters)
            load_stage_bf16(smem_base, j % STAGES, j, m_base, n_base, K, tid);
        cp_commit();
    }

    // ---------------- epilogue ----------------
    float wss[8], bv[8];
    #pragma unroll
    for (int nt = 0; nt < 4; nt++) {
        #pragma unroll
        for (int j = 0; j < 2; j++) {
            int n = n_base + wn * 32 + nt * 8 + (lane & 3) * 2 + j;
            wss[nt * 2 + j] = g_ws[n];
            bv[nt * 2 + j]  = bias[n];
        }
    }
    #pragma unroll
    for (int mt = 0; mt < 4; mt++) {
        #pragma unroll
        for (int p = 0; p < 2; p++) {
            int m = m_base + wm * 64 + mt * 16 + (lane >> 2) + p * 8;
            float cs = g_xs[m];
            float* orow = out + (size_t)m * N + n_base + wn * 32;
            #pragma unroll
            for (int nt = 0; nt < 4; nt++) {
                float2 o;
                o.x = acc[mt][nt][p * 2 + 0] * (cs * wss[nt * 2 + 0]) + bv[nt * 2 + 0];
                o.y = acc[mt][nt][p * 2 + 1] * (cs * wss[nt * 2 + 1]) + bv[nt * 2 + 1];
                *reinterpret_cast<float2*>(orow + nt * 8 + (lane & 3) * 2) = o;
            }
        }
    }
}

// ---------------- launcher ----------------
extern "C" void kernel_launch(void* const* d_in, const int* in_sizes, int n_in,
                              void* d_out, int out_size) {
    const float* x    = (const float*)d_in[0];
    const float* w    = (const float*)d_in[1];
    const float* bias = (const float*)d_in[2];
    int N = in_sizes[2];                  // 4096
    int K = in_sizes[1] / N;              // 4096
    int M = in_sizes[0] / K;              // 8192

    quant_w_kernel<<<N, 256>>>(w, K);
    quant_x_kernel<<<M, 256>>>(x, K);

    cudaFuncSetAttribute(qgemm_kernel, cudaFuncAttributeMaxDynamicSharedMemorySize,
                         GEMM_SMEM);
    dim3 grid(N / BN, M / BM);
    qgemm_kernel<<<grid, 256, GEMM_SMEM>>>(bias, (float*)d_out, M, N, K);
}

// round 4
// speedup vs baseline: 2.5755x; 1.0507x over previous
#include <cuda_runtime.h>
#include <cuda_bf16.h>
#include <cstdint>
#include <cstddef>

// ---------------- problem constants ----------------
#define MAXM 8192
#define MAXN 4096
#define MAXK 4096

// quantized operands in device globals (allocation-free scratch)
// g_Xq holds (Xq - zp): exact integers in [-255,255], bf16-exact.
// g_Wq holds Wq:        exact integers in [-127,127], bf16-exact.
__device__ __nv_bfloat16 g_Xq[(size_t)MAXM * MAXK];
__device__ __nv_bfloat16 g_Wq[(size_t)MAXN * MAXK];
__device__ float g_xs[MAXM];   // activation scale per token
__device__ float g_ws[MAXN];   // weight scale per row

// ---------------- helpers ----------------
__device__ __forceinline__ uint32_t smem_u32(const void* p) {
    return (uint32_t)__cvta_generic_to_shared(p);
}
__device__ __forceinline__ void cp16(uint32_t dst, const void* src) {
    asm volatile("cp.async.cg.shared.global [%0], [%1], 16;"
                 :: "r"(dst), "l"(__cvta_generic_to_global(src)) : "memory");
}
__device__ __forceinline__ void cp_commit() {
    asm volatile("cp.async.commit_group;" ::: "memory");
}
template <int N>
__device__ __forceinline__ void cp_wait_group() {
    asm volatile("cp.async.wait_group %0;" :: "n"(N) : "memory");
}
__device__ __forceinline__ void ldsm4(uint32_t& r0, uint32_t& r1, uint32_t& r2,
                                      uint32_t& r3, uint32_t addr) {
    asm volatile("ldmatrix.sync.aligned.m8n8.x4.shared.b16 {%0,%1,%2,%3}, [%4];"
                 : "=r"(r0), "=r"(r1), "=r"(r2), "=r"(r3) : "r"(addr));
}
__device__ __forceinline__ void hmma16816(float* d, const uint32_t* a,
                                          uint32_t b0, uint32_t b1) {
    asm volatile(
        "mma.sync.aligned.m16n8k16.row.col.f32.bf16.bf16.f32 "
        "{%0,%1,%2,%3}, {%4,%5,%6,%7}, {%8,%9}, {%0,%1,%2,%3};"
        : "+f"(d[0]), "+f"(d[1]), "+f"(d[2]), "+f"(d[3])
        : "r"(a[0]), "r"(a[1]), "r"(a[2]), "r"(a[3]), "r"(b0), "r"(b1));
}

// ---------------- block reductions ----------------
__device__ __forceinline__ float blockReduceMaxF(float v) {
    __shared__ float sh[8];
    #pragma unroll
    for (int o = 16; o; o >>= 1) v = fmaxf(v, __shfl_xor_sync(0xffffffffu, v, o));
    int wid = threadIdx.x >> 5, lid = threadIdx.x & 31;
    if (lid == 0) sh[wid] = v;
    __syncthreads();
    if (threadIdx.x < 32) {
        float t = (lid < 8) ? sh[lid] : -3.4e38f;
        #pragma unroll
        for (int o = 4; o; o >>= 1) t = fmaxf(t, __shfl_xor_sync(0xffffffffu, t, o));
        if (lid == 0) sh[0] = t;
    }
    __syncthreads();
    float r = sh[0];
    __syncthreads();
    return r;
}

// ---------------- quantization kernels ----------------
__global__ void __launch_bounds__(256) quant_w_kernel(const float* __restrict__ W, int K) {
    int n = blockIdx.x;
    const float4* row = (const float4*)(W + (size_t)n * K);
    int nv = K >> 2;
    float amax = 0.f;
    for (int i = threadIdx.x; i < nv; i += blockDim.x) {
        float4 v = row[i];
        amax = fmaxf(amax, fmaxf(fmaxf(fabsf(v.x), fabsf(v.y)),
                                 fmaxf(fabsf(v.z), fabsf(v.w))));
    }
    amax = blockReduceMaxF(amax);
    float scale = (amax > 0.f) ? (amax / 127.0f) : 1.0f;
    if (threadIdx.x == 0) g_ws[n] = scale;
    __nv_bfloat16* o = g_Wq + (size_t)n * K;
    for (int i = threadIdx.x; i < nv; i += blockDim.x) {
        float4 v = row[i];
        float q0 = fminf(fmaxf(rintf(v.x / scale), -127.f), 127.f);
        float q1 = fminf(fmaxf(rintf(v.y / scale), -127.f), 127.f);
        float q2 = fminf(fmaxf(rintf(v.z / scale), -127.f), 127.f);
        float q3 = fminf(fmaxf(rintf(v.w / scale), -127.f), 127.f);
        uint2 u;
        u.x = ((uint32_t)__bfloat16_as_ushort(__float2bfloat16(q1)) << 16) |
               (uint32_t)__bfloat16_as_ushort(__float2bfloat16(q0));
        u.y = ((uint32_t)__bfloat16_as_ushort(__float2bfloat16(q3)) << 16) |
               (uint32_t)__bfloat16_as_ushort(__float2bfloat16(q2));
        *reinterpret_cast<uint2*>(o + 4 * (size_t)i) = u;
    }
}

__global__ void __launch_bounds__(256) quant_x_kernel(const float* __restrict__ X, int K) {
    int m = blockIdx.x;
    const float4* row = (const float4*)(X + (size_t)m * K);
    int nv = K >> 2;
    float vmax = -3.4e38f, nvmin = -3.4e38f;  // nvmin = max(-x)
    for (int i = threadIdx.x; i < nv; i += blockDim.x) {
        float4 v = row[i];
        vmax  = fmaxf(vmax,  fmaxf(fmaxf(v.x, v.y), fmaxf(v.z, v.w)));
        nvmin = fmaxf(nvmin, fmaxf(fmaxf(-v.x, -v.y), fmaxf(-v.z, -v.w)));
    }
    vmax  = blockReduceMaxF(vmax);
    nvmin = blockReduceMaxF(nvmin);
    float vmin = -nvmin;
    float rng = vmax - vmin;
    float scale = (rng > 0.f) ? (rng / 255.0f) : 1.0f;
    float zp = rintf(-vmin / scale);
    if (threadIdx.x == 0) g_xs[m] = scale;
    __nv_bfloat16* o = g_Xq + (size_t)m * K;
    for (int i = threadIdx.x; i < nv; i += blockDim.x) {
        float4 v = row[i];
        // (clip(round(x/s)+zp, 0, 255) - zp) : exact integer in [-255,255]
        float q0 = fminf(fmaxf(rintf(v.x / scale) + zp, 0.f), 255.f) - zp;
        float q1 = fminf(fmaxf(rintf(v.y / scale) + zp, 0.f), 255.f) - zp;
        float q2 = fminf(fmaxf(rintf(v.z / scale) + zp, 0.f), 255.f) - zp;
        float q3 = fminf(fmaxf(rintf(v.w / scale) + zp, 0.f), 255.f) - zp;
        uint2 u;
        u.x = ((uint32_t)__bfloat16_as_ushort(__float2bfloat16(q1)) << 16) |
               (uint32_t)__bfloat16_as_ushort(__float2bfloat16(q0));
        u.y = ((uint32_t)__bfloat16_as_ushort(__float2bfloat16(q3)) << 16) |
               (uint32_t)__bfloat16_as_ushort(__float2bfloat16(q2));
        *reinterpret_cast<uint2*>(o + 4 * (size_t)i) = u;
    }
}

// ---------------- bf16 GEMM (HMMA via mma.sync) ----------------
#define BM 128
#define BN 256
#define BK 64                          // bf16 elems per K-chunk = 128 bytes/row
#define STAGES 3
#define AS_BYTES (BM * 128)            // 16 KB
#define BS_BYTES (BN * 128)            // 32 KB
#define STAGE_BYTES (AS_BYTES + BS_BYTES)   // 48 KB
#define GEMM_SMEM (STAGES * STAGE_BYTES)    // 144 KB

__device__ __forceinline__ void load_stage_bf16(uint32_t smem_base, int s, int kc,
                                                int m_base, int n_base, int K, int tid) {
    uint32_t a_smem = smem_base + s * STAGE_BYTES;
    uint32_t b_smem = a_smem + AS_BYTES;
    const char* Abase = (const char*)g_Xq;
    const char* Bbase = (const char*)g_Wq;
    size_t koff = (size_t)kc * BK * 2;     // bytes
    // A: 128 rows x 8 x 16B = 1024 chunks / 256 threads = 4 each
    #pragma unroll
    for (int it = 0; it < 4; it++) {
        int c = tid + it * 256;
        int row = c >> 3, ch = c & 7;
        const void* src = Abase + ((size_t)(m_base + row) * K) * 2 + koff + ch * 16;
        cp16(a_smem + row * 128 + ((ch ^ (row & 7)) * 16), src);
    }
    // B: 256 rows x 8 x 16B = 2048 chunks / 256 threads = 8 each
    #pragma unroll
    for (int it = 0; it < 8; it++) {
        int c = tid + it * 256;
        int row = c >> 3, ch = c & 7;
        const void* src = Bbase + ((size_t)(n_base + row) * K) * 2 + koff + ch * 16;
        cp16(b_smem + row * 128 + ((ch ^ (row & 7)) * 16), src);
    }
}

__global__ void __launch_bounds__(256, 1)
qgemm_kernel(const float* __restrict__ bias, float* __restrict__ out,
             int M, int N, int K) {
    extern __shared__ char smem[];
    const int tid  = threadIdx.x;
    const int wid  = tid >> 5;
    const int lane = tid & 31;
    const int wm   = wid >> 2;        // 0..1  (64-row slab)
    const int wn   = wid & 3;         // 0..3  (64-col slab)
    uint32_t smem_base = smem_u32(smem);

    const int m_base = blockIdx.y * BM;
    const int n_base = blockIdx.x * BN;

    float acc[4][8][4];               // [mt][nt][reg], nt = n8 block 0..7
    #pragma unroll
    for (int mt = 0; mt < 4; mt++)
        #pragma unroll
        for (int nt = 0; nt < 8; nt++)
            #pragma unroll
            for (int r = 0; r < 4; r++) acc[mt][nt][r] = 0.f;

    const int iters = K / BK;         // 64

    // per-thread invariant addressing
    const int rowA  = wm * 64 + (lane & 15);   // + mt*16
    const int halfA = lane >> 4;               // 16B chunk low bit (k half)
    const int swzA  = rowA & 7;
    const int rowB0 = wn * 64 + (lane & 15);   // + nq*16
    const int swzB  = lane & 7;

    #pragma unroll
    for (int i = 0; i < STAGES - 1; i++) {
        load_stage_bf16(smem_base, i, i, m_base, n_base, K, tid);
        cp_commit();
    }

    for (int i = 0; i < iters; i++) {
        int s = i % STAGES;
        cp_wait_group<STAGES - 2>();
        __syncthreads();

        uint32_t a_base = smem_base + s * STAGE_BYTES;
        uint32_t b_base = a_base + AS_BYTES;

        #pragma unroll
        for (int ks = 0; ks < 4; ks++) {
            // B: 4 ldsm.x4 covering n64 at this k16 step
            uint32_t bq[4][4];
            #pragma unroll
            for (int nq = 0; nq < 4; nq++)
                ldsm4(bq[nq][0], bq[nq][1], bq[nq][2], bq[nq][3],
                      b_base + (rowB0 + nq * 16) * 128 +
                      (((2 * ks + halfA) ^ swzB) * 16));
            #pragma unroll
            for (int mt = 0; mt < 4; mt++) {
                uint32_t a[4];
                ldsm4(a[0], a[1], a[2], a[3],
                      a_base + (rowA + mt * 16) * 128 +
                      (((2 * ks + halfA) ^ swzA) * 16));
                #pragma unroll
                for (int nq = 0; nq < 4; nq++) {
                    hmma16816(acc[mt][nq * 2 + 0], a, bq[nq][0], bq[nq][2]);
                    hmma16816(acc[mt][nq * 2 + 1], a, bq[nq][1], bq[nq][3]);
                }
            }
        }

        int j = i + STAGES - 1;
        if (j < iters)
            load_stage_bf16(smem_base, j % STAGES, j, m_base, n_base, K, tid);
        cp_commit();
    }

    // ---------------- epilogue ----------------
    #pragma unroll
    for (int mt = 0; mt < 4; mt++) {
        #pragma unroll
        for (int p = 0; p < 2; p++) {
            int m = m_base + wm * 64 + mt * 16 + (lane >> 2) + p * 8;
            float cs = g_xs[m];
            float* orow = out + (size_t)m * N + n_base + wn * 64;
            #pragma unroll
            for (int nt = 0; nt < 8; nt++) {
                int nc = nt * 8 + (lane & 3) * 2;
                int n  = n_base + wn * 64 + nc;
                float2 o;
                o.x = acc[mt][nt][p * 2 + 0] * (cs * g_ws[n + 0]) + bias[n + 0];
                o.y = acc[mt][nt][p * 2 + 1] * (cs * g_ws[n + 1]) + bias[n + 1];
                *reinterpret_cast<float2*>(orow + nc) = o;
            }
        }
    }
}

// ---------------- launcher ----------------
extern "C" void kernel_launch(void* const* d_in, const int* in_sizes, int n_in,
                              void* d_out, int out_size) {
    const float* x    = (const float*)d_in[0];
    const float* w    = (const float*)d_in[1];
    const float* bias = (const float*)d_in[2];
    int N = in_sizes[2];                  // 4096
    int K = in_sizes[1] / N;              // 4096
    int M = in_sizes[0] / K;              // 8192

    quant_w_kernel<<<N, 256>>>(w, K);
    quant_x_kernel<<<M, 256>>>(x, K);

    cudaFuncSetAttribute(qgemm_kernel, cudaFuncAttributeMaxDynamicSharedMemorySize,
                         GEMM_SMEM);
    dim3 grid(N / BN, M / BM);
    qgemm_kernel<<<grid, 256, GEMM_SMEM>>>(bias, (float*)d_out, M, N, K);
}